// round 2
// baseline (speedup 1.0000x reference)
#include <cuda_runtime.h>
#include <cuda_bf16.h>
#include <math.h>

// Problem shapes (fixed by the dataset)
#define BDIM 8
#define NDIM 8192
#define CDIM 256
#define HDIM 256
#define ODIM 256
#define KDIM 64
#define KCHUNK 4
#define NCHUNKS (KDIM / KCHUNK)   // 16
#define LEAKY_ALPHA 0.3f
#define EPS 1e-6f

// Scratch for per-(b, kchunk) partial weighted hidden sums: 8*16*256 floats = 128 KB
__device__ float g_partial[BDIM * NCHUNKS * HDIM];

__device__ __forceinline__ float leaky(float x) {
    return x >= 0.0f ? x : LEAKY_ALPHA * x;
}

// Kernel 1: for each (b, kchunk of 4 neighbors), compute
//   partial[b][chunk][h] = sum_{k in chunk} w[k] * leaky(dot(emb[b,nb[k],:], Qw[:,h]) + Qb[h])
// Thread layout: tk = tid/64 selects which of the 4 neighbors, th = tid%64 selects
// a group of 4 consecutive h (float4 on Qw rows -> fully coalesced LDG.128).
__global__ void __launch_bounds__(256, 1)
k1_neighbor_hidden(const float* __restrict__ emb,
                   const float* __restrict__ weights,
                   const float* __restrict__ Qw,
                   const float* __restrict__ Qb,
                   const int*   __restrict__ nb,
                   const int*   __restrict__ nid_p)
{
    const int chunk = blockIdx.x;   // 0..15
    const int b     = blockIdx.y;   // 0..7
    const int tid   = threadIdx.x;
    const int tk    = tid >> 6;     // 0..3
    const int th    = tid & 63;     // 0..63  -> h = 4*th .. 4*th+3

    __shared__ float embs[KCHUNK][CDIM];   // 4 KB
    __shared__ float ws[KCHUNK];
    __shared__ int   nbs[KCHUNK];
    __shared__ float4 part[KCHUNK][64];    // 4 KB

    const int nid = *nid_p;

    if (tid < KCHUNK) {
        int n = nb[chunk * KCHUNK + tid];
        nbs[tid] = n;
        ws[tid] = weights[(size_t)n * NDIM + nid];
    }
    __syncthreads();

    // Cooperative load of 4 embedding rows (float4: 256 threads x 16B = 4 KB)
    {
        const float4* src =
            (const float4*)(emb + ((size_t)b * NDIM + nbs[tk]) * CDIM);
        ((float4*)embs[tk])[th] = src[th];
    }
    __syncthreads();

    const float4* Qw4 = (const float4*)Qw;   // Qw is (C,H) row-major; row c: 64 float4
    const float*  er  = embs[tk];

    float4 acc = make_float4(0.f, 0.f, 0.f, 0.f);
    #pragma unroll 8
    for (int c = 0; c < CDIM; c++) {
        float  e = er[c];
        float4 q = __ldg(&Qw4[c * 64 + th]);
        acc.x = fmaf(e, q.x, acc.x);
        acc.y = fmaf(e, q.y, acc.y);
        acc.z = fmaf(e, q.z, acc.z);
        acc.w = fmaf(e, q.w, acc.w);
    }

    const float4 qb = ((const float4*)Qb)[th];
    const float  w  = ws[tk];
    acc.x = leaky(acc.x + qb.x) * w;
    acc.y = leaky(acc.y + qb.y) * w;
    acc.z = leaky(acc.z + qb.z) * w;
    acc.w = leaky(acc.w + qb.w) * w;

    part[tk][th] = acc;
    __syncthreads();

    if (tk == 0) {
        float4 s  = part[0][th];
        float4 s1 = part[1][th];
        float4 s2 = part[2][th];
        float4 s3 = part[3][th];
        s.x += s1.x + s2.x + s3.x;
        s.y += s1.y + s2.y + s3.y;
        s.z += s1.z + s2.z + s3.z;
        s.w += s1.w + s2.w + s3.w;
        ((float4*)(g_partial + ((size_t)b * NCHUNKS + chunk) * HDIM))[th] = s;
    }
}

// Kernel 2: per batch b —
//   wsum[h]   = (sum_chunk partial[b][chunk][h]) / (sum_k w[k] + EPS)
//   concat    = [emb[b,node_id,:], wsum]  (512)
//   v[o]      = leaky(dot(concat, Ww[:,o]) + Wb[o])
//   out[b,o]  = v[o] / (||v||_2 + EPS)
__global__ void __launch_bounds__(256, 1)
k2_finalize(const float* __restrict__ emb,
            const float* __restrict__ weights,
            const float* __restrict__ Ww,
            const float* __restrict__ Wb,
            const int*   __restrict__ nb,
            const int*   __restrict__ nid_p,
            float*       __restrict__ out)
{
    const int b   = blockIdx.x;
    const int tid = threadIdx.x;

    __shared__ float concat[CDIM + HDIM];   // 512 floats
    __shared__ float warr[KDIM];
    __shared__ float denom_s;
    __shared__ float4 red[4][64];
    __shared__ float ssr[64];
    __shared__ float norm_s;

    const int nid = *nid_p;

    // node embedding -> concat[0..255]
    concat[tid] = emb[((size_t)b * NDIM + nid) * CDIM + tid];

    if (tid < KDIM) {
        warr[tid] = weights[(size_t)nb[tid] * NDIM + nid];
    }

    // partial reduction over the 16 chunks (independent of denom)
    float s = 0.0f;
    #pragma unroll
    for (int ch = 0; ch < NCHUNKS; ch++) {
        s += g_partial[((size_t)b * NCHUNKS + ch) * HDIM + tid];
    }
    __syncthreads();

    if (tid == 0) {
        float d = 0.0f;
        #pragma unroll
        for (int k = 0; k < KDIM; k++) d += warr[k];
        denom_s = d + EPS;
    }
    __syncthreads();

    concat[CDIM + tid] = s / denom_s;
    __syncthreads();

    // GEMV: 512 x 256, split c-range 4 ways, float4 over o.
    const int tc = tid >> 6;    // 0..3 : which 128-wide c segment
    const int to = tid & 63;    // 0..63: o = 4*to .. 4*to+3
    const float4* Ww4 = (const float4*)Ww;   // (512,256) row-major; row c: 64 float4

    float4 acc = make_float4(0.f, 0.f, 0.f, 0.f);
    const int c0 = tc * 128;
    #pragma unroll 8
    for (int c = c0; c < c0 + 128; c++) {
        float  e = concat[c];
        float4 q = __ldg(&Ww4[c * 64 + to]);
        acc.x = fmaf(e, q.x, acc.x);
        acc.y = fmaf(e, q.y, acc.y);
        acc.z = fmaf(e, q.z, acc.z);
        acc.w = fmaf(e, q.w, acc.w);
    }
    red[tc][to] = acc;
    __syncthreads();

    float4 v = make_float4(0.f, 0.f, 0.f, 0.f);
    if (tid < 64) {
        float4 r0 = red[0][tid], r1 = red[1][tid], r2 = red[2][tid], r3 = red[3][tid];
        float4 wb = ((const float4*)Wb)[tid];
        v.x = leaky(r0.x + r1.x + r2.x + r3.x + wb.x);
        v.y = leaky(r0.y + r1.y + r2.y + r3.y + wb.y);
        v.z = leaky(r0.z + r1.z + r2.z + r3.z + wb.z);
        v.w = leaky(r0.w + r1.w + r2.w + r3.w + wb.w);
        ssr[tid] = v.x * v.x + v.y * v.y + v.z * v.z + v.w * v.w;
    }
    __syncthreads();

    if (tid == 0) {
        float t = 0.0f;
        #pragma unroll
        for (int i = 0; i < 64; i++) t += ssr[i];
        norm_s = sqrtf(t) + EPS;
    }
    __syncthreads();

    if (tid < 64) {
        float inv = 1.0f / norm_s;
        v.x *= inv; v.y *= inv; v.z *= inv; v.w *= inv;
        ((float4*)(out + (size_t)b * ODIM))[tid] = v;
    }
}

extern "C" void kernel_launch(void* const* d_in, const int* in_sizes, int n_in,
                              void* d_out, int out_size)
{
    const float* emb     = (const float*)d_in[0];
    const float* weights = (const float*)d_in[1];
    const float* Qw      = (const float*)d_in[2];
    const float* Qb      = (const float*)d_in[3];
    const float* Ww      = (const float*)d_in[4];
    const float* Wb      = (const float*)d_in[5];
    const int*   nb      = (const int*)d_in[6];
    const int*   nid     = (const int*)d_in[7];
    float*       out     = (float*)d_out;

    dim3 g1(NCHUNKS, BDIM);   // 16 x 8 = 128 blocks
    k1_neighbor_hidden<<<g1, 256>>>(emb, weights, Qw, Qb, nb, nid);
    k2_finalize<<<BDIM, 256>>>(emb, weights, Ww, Wb, nb, nid, out);
}

// round 3
// speedup vs baseline: 1.2448x; 1.2448x over previous
#include <cuda_runtime.h>
#include <cuda_bf16.h>
#include <math.h>

// Problem shapes (fixed by the dataset)
#define BDIM 8
#define NDIM 8192
#define CDIM 256
#define HDIM 256
#define ODIM 256
#define KDIM 64
#define KCHUNK 4
#define NCHUNKS (KDIM / KCHUNK)   // 16
#define LEAKY_ALPHA 0.3f
#define EPS 1e-6f

// Scratch: per-(b, kchunk) partial weighted hidden sums: 8*16*256 floats = 128 KB
__device__ float g_partial[BDIM * NCHUNKS * HDIM];

__device__ __forceinline__ float leaky(float x) {
    return x >= 0.0f ? x : LEAKY_ALPHA * x;
}

// ---------------------------------------------------------------------------
// Kernel 1: grid (16 chunks, 8 batches), 512 threads.
// Thread layout: th = tid&63 (h-group of 4, float4), tc = (tid>>6)&1 (c half),
//                tk = tid>>7 (neighbor within chunk).
// Each thread computes a PARTIAL dot (its 128-c half); partials are combined
// in smem BEFORE bias + leaky (nonlinearity must see the full dot).
// ---------------------------------------------------------------------------
__global__ void __launch_bounds__(512, 1)
k1_neighbor_hidden(const float* __restrict__ emb,
                   const float* __restrict__ weights,
                   const float* __restrict__ Qw,
                   const float* __restrict__ Qb,
                   const int*   __restrict__ nb,
                   const int*   __restrict__ nid_p)
{
    const int chunk = blockIdx.x;   // 0..15
    const int b     = blockIdx.y;   // 0..7
    const int tid   = threadIdx.x;
    const int th    = tid & 63;         // h-group
    const int tc    = (tid >> 6) & 1;   // c half
    const int tk    = tid >> 7;         // neighbor 0..3

    __shared__ float  embs[KCHUNK][CDIM];  // 4 KB
    __shared__ float  ws[KCHUNK];
    __shared__ int    nbs[KCHUNK];
    __shared__ float4 part[KCHUNK * 2][64]; // 8 KB, slot = tk*2+tc

    const int nid = *nid_p;

    if (tid < KCHUNK) {
        int n = nb[chunk * KCHUNK + tid];
        nbs[tid] = n;
        ws[tid] = weights[(size_t)n * NDIM + nid];
    }
    __syncthreads();

    // Cooperative load of 4 embedding rows (256 float4 total; tid<256 do one each)
    if (tid < 256) {
        int r = tid >> 6, col = tid & 63;
        ((float4*)embs[r])[col] =
            ((const float4*)(emb + ((size_t)b * NDIM + nbs[r]) * CDIM))[col];
    }
    __syncthreads();

    const float*  er  = embs[tk] + tc * 128;
    const float4* Qw4 = (const float4*)Qw + (size_t)tc * 128 * 64;

    float4 acc = make_float4(0.f, 0.f, 0.f, 0.f);
    #pragma unroll 16
    for (int c = 0; c < 128; c++) {
        float  e = er[c];
        float4 q = __ldg(&Qw4[c * 64 + th]);
        acc.x = fmaf(e, q.x, acc.x);
        acc.y = fmaf(e, q.y, acc.y);
        acc.z = fmaf(e, q.z, acc.z);
        acc.w = fmaf(e, q.w, acc.w);
    }
    part[tk * 2 + tc][th] = acc;
    __syncthreads();

    // Combine c-halves, apply bias + leaky + neighbor weight. (k,h) disjoint per thread.
    if (tid < 256) {
        int k = tid >> 6, h = tid & 63;
        float4 a0 = part[k * 2 + 0][h];
        float4 a1 = part[k * 2 + 1][h];
        float4 qb = ((const float4*)Qb)[h];
        float  w  = ws[k];
        float4 r;
        r.x = leaky(a0.x + a1.x + qb.x) * w;
        r.y = leaky(a0.y + a1.y + qb.y) * w;
        r.z = leaky(a0.z + a1.z + qb.z) * w;
        r.w = leaky(a0.w + a1.w + qb.w) * w;
        part[k * 2][h] = r;
    }
    __syncthreads();

    // Sum the 4 neighbors of this chunk, write partial to global scratch.
    if (tid < 64) {
        float4 s0 = part[0][tid], s1 = part[2][tid], s2 = part[4][tid], s3 = part[6][tid];
        float4 s;
        s.x = s0.x + s1.x + s2.x + s3.x;
        s.y = s0.y + s1.y + s2.y + s3.y;
        s.z = s0.z + s1.z + s2.z + s3.z;
        s.w = s0.w + s1.w + s2.w + s3.w;
        ((float4*)(g_partial + ((size_t)b * NCHUNKS + chunk) * HDIM))[tid] = s;
    }
}

// ---------------------------------------------------------------------------
// Kernel 2: grid 8 (one block per batch), 1024 threads.
// Front-end (parallel, disjoint thread ranges):
//   tid <  64          : node embedding -> concat[0..255] (float4)
//   tid in [256,512)   : wsum[h] = sum over 16 chunk partials
//   tid in [512,576)   : gather w[k], warp-shuffle reduce -> denom
// GEMV: 512x256 split 16 ways over c (32 c per thread), float4 over o.
// Final: smem reduce 16 partials, bias+leaky, warp-shuffle norm, store.
// ---------------------------------------------------------------------------
__global__ void __launch_bounds__(1024, 1)
k2_finalize(const float* __restrict__ emb,
            const float* __restrict__ weights,
            const float* __restrict__ Ww,
            const float* __restrict__ Wb,
            const int*   __restrict__ nb,
            const int*   __restrict__ nid_p,
            float*       __restrict__ out)
{
    const int b   = blockIdx.x;
    const int tid = threadIdx.x;

    __shared__ float  concat[CDIM + HDIM];  // 512 floats
    __shared__ float  wpart[2];
    __shared__ float  denom_s;
    __shared__ float4 red[16][64];          // 16 KB
    __shared__ float  nrm[2];

    const int nid = *nid_p;

    float myws = 0.0f;

    if (tid < 64) {
        ((float4*)concat)[tid] =
            ((const float4*)(emb + ((size_t)b * NDIM + nid) * CDIM))[tid];
    } else if (tid >= 256 && tid < 512) {
        const int h = tid - 256;
        const float* gp = g_partial + (size_t)b * NCHUNKS * HDIM + h;
        float s = 0.0f;
        #pragma unroll
        for (int ch = 0; ch < NCHUNKS; ch++) s += gp[ch * HDIM];
        myws = s;
    } else if (tid >= 512 && tid < 576) {
        const int k = tid - 512;
        float wk = weights[(size_t)nb[k] * NDIM + nid];
        // full-warp shuffle reduction (warps 16 and 17)
        #pragma unroll
        for (int off = 16; off > 0; off >>= 1)
            wk += __shfl_xor_sync(0xFFFFFFFFu, wk, off);
        if ((tid & 31) == 0) wpart[(tid - 512) >> 5] = wk;
    }
    __syncthreads();

    if (tid == 0) denom_s = wpart[0] + wpart[1] + EPS;
    __syncthreads();

    if (tid >= 256 && tid < 512) concat[tid] = myws / denom_s;
    __syncthreads();

    // GEMV: c-split 16 ways
    const int tc = tid >> 6;    // 0..15 -> c in [tc*32, tc*32+32)
    const int to = tid & 63;    // o-group (float4)
    const float4* Ww4 = (const float4*)Ww;

    float4 acc = make_float4(0.f, 0.f, 0.f, 0.f);
    const int c0 = tc * 32;
    #pragma unroll 8
    for (int c = c0; c < c0 + 32; c++) {
        float  e = concat[c];
        float4 q = __ldg(&Ww4[c * 64 + to]);
        acc.x = fmaf(e, q.x, acc.x);
        acc.y = fmaf(e, q.y, acc.y);
        acc.z = fmaf(e, q.z, acc.z);
        acc.w = fmaf(e, q.w, acc.w);
    }
    red[tc][to] = acc;
    __syncthreads();

    float4 v = make_float4(0.f, 0.f, 0.f, 0.f);
    if (tid < 64) {
        float4 s = red[0][tid];
        #pragma unroll
        for (int i = 1; i < 16; i++) {
            float4 r = red[i][tid];
            s.x += r.x; s.y += r.y; s.z += r.z; s.w += r.w;
        }
        float4 wb = ((const float4*)Wb)[tid];
        v.x = leaky(s.x + wb.x);
        v.y = leaky(s.y + wb.y);
        v.z = leaky(s.z + wb.z);
        v.w = leaky(s.w + wb.w);
        float ssq = v.x * v.x + v.y * v.y + v.z * v.z + v.w * v.w;
        #pragma unroll
        for (int off = 16; off > 0; off >>= 1)
            ssq += __shfl_xor_sync(0xFFFFFFFFu, ssq, off);
        if ((tid & 31) == 0) nrm[tid >> 5] = ssq;
    }
    __syncthreads();

    if (tid < 64) {
        float inv = 1.0f / (sqrtf(nrm[0] + nrm[1]) + EPS);
        v.x *= inv; v.y *= inv; v.z *= inv; v.w *= inv;
        ((float4*)(out + (size_t)b * ODIM))[tid] = v;
    }
}

extern "C" void kernel_launch(void* const* d_in, const int* in_sizes, int n_in,
                              void* d_out, int out_size)
{
    const float* emb     = (const float*)d_in[0];
    const float* weights = (const float*)d_in[1];
    const float* Qw      = (const float*)d_in[2];
    const float* Qb      = (const float*)d_in[3];
    const float* Ww      = (const float*)d_in[4];
    const float* Wb      = (const float*)d_in[5];
    const int*   nb      = (const int*)d_in[6];
    const int*   nid     = (const int*)d_in[7];
    float*       out     = (float*)d_out;

    dim3 g1(NCHUNKS, BDIM);   // 16 x 8 = 128 blocks
    k1_neighbor_hidden<<<g1, 512>>>(emb, weights, Qw, Qb, nb, nid);
    k2_finalize<<<BDIM, 1024>>>(emb, weights, Ww, Wb, nb, nid, out);
}